// round 1
// baseline (speedup 1.0000x reference)
#include <cuda_runtime.h>

#define B    8
#define T    512
#define U1   65
#define V    128
#define ENC  512
#define PRED 256
#define JOIN 512
#define NTOK 64

// ---- device scratch (no allocations allowed) ----
__device__ float g_pp[B * U1 * JOIN];   // pred_proj + bj1   (1.06 MB)
__device__ float g_ep[B * T * JOIN];    // enc_proj          (8.4 MB)
__device__ float g_wt[V * JOIN];        // Wj2 transposed    (256 KB)

// ---------------- Wj2 transpose: g_wt[v][k] = Wj2[k][v] ----------------
__global__ void k_wt(const float* __restrict__ Wj2) {
    int idx = blockIdx.x * 256 + threadIdx.x;   // 65536 elements
    int k = idx >> 7, v = idx & 127;
    g_wt[v * JOIN + k] = Wj2[idx];
}

// ---------------- prediction network + pred_proj (+bj1) ----------------
// grid = B*U1 (520), block = 512
__global__ void k_pred(const void* __restrict__ targets_raw,
                       const float* __restrict__ emb,
                       const float* __restrict__ W1, const float* __restrict__ b1,
                       const float* __restrict__ W2, const float* __restrict__ b2,
                       const float* __restrict__ Wj1, const float* __restrict__ bj1) {
    int b = blockIdx.x / U1;
    int u = blockIdx.x % U1;
    int tid = threadIdx.x;

    __shared__ float s_e[2 * 128];
    __shared__ float s_p[PRED];
    __shared__ float s_q[PRED];
    __shared__ int   s_is64;

    // detect int64 vs int32 targets buffer: if int64, odd 32-bit words
    // (high halves of small nonneg values) are all zero.
    if (tid == 0) {
        const int* w = (const int*)targets_raw;
        int z = 0;
        #pragma unroll
        for (int i = 1; i < 64; i += 2) z |= w[i];
        s_is64 = (z == 0) ? 1 : 0;
    }
    __syncthreads();
    int is64 = s_is64;

    if (tid < 2 * 128) {
        int half = tid >> 7;           // 0 -> targets[u-1], 1 -> targets[u-2]
        int ei   = tid & 127;
        int idx  = u - 1 - half;
        int tok  = V - 1;              // pad token
        if (idx >= 0) {
            if (is64) tok = (int)((const long long*)targets_raw)[b * NTOK + idx];
            else      tok = ((const int*)targets_raw)[b * NTOK + idx];
        }
        s_e[tid] = emb[tok * 128 + ei];
    }
    __syncthreads();

    if (tid < PRED) {
        float acc = b1[tid];
        #pragma unroll 8
        for (int k = 0; k < 2 * 128; k++) acc = fmaf(s_e[k], W1[k * PRED + tid], acc);
        s_p[tid] = fmaxf(acc, 0.f);
    }
    __syncthreads();

    if (tid < PRED) {
        float acc = b2[tid];
        #pragma unroll 8
        for (int k = 0; k < PRED; k++) acc = fmaf(s_p[k], W2[k * PRED + tid], acc);
        s_q[tid] = fmaxf(acc, 0.f);
    }
    __syncthreads();

    // pred_proj[j] = sum_p pred[p] * Wj1[ENC+p][j] + bj1[j]
    {
        float acc = bj1[tid];
        const float* Wp = Wj1 + (size_t)ENC * JOIN;
        #pragma unroll 8
        for (int p = 0; p < PRED; p++) acc = fmaf(s_q[p], Wp[p * JOIN + tid], acc);
        g_pp[(b * U1 + u) * JOIN + tid] = acc;
    }
}

// ---------------- enc_proj: g_ep[b][t][j] = enc[b][t] @ Wj1[:ENC] ----------------
// grid = B*T/8 (512), block = 512, 8 rows register-tiled; skips t >= enc_size
__global__ void k_encproj(const float* __restrict__ enc,
                          const int* __restrict__ es_arr,
                          const float* __restrict__ Wj1) {
    int b  = blockIdx.x >> 6;
    int t0 = (blockIdx.x & 63) << 3;
    int es = es_arr[b];
    if (t0 >= es) return;
    int nt = min(8, es - t0);

    __shared__ float s_x[8][ENC];
    int tid = threadIdx.x;
    for (int r = 0; r < nt; r++)
        s_x[r][tid] = enc[((size_t)(b * T + t0 + r)) * ENC + tid];
    __syncthreads();

    float acc[8] = {0.f, 0.f, 0.f, 0.f, 0.f, 0.f, 0.f, 0.f};
    #pragma unroll 4
    for (int k = 0; k < ENC; k++) {
        float w = Wj1[k * JOIN + tid];
        #pragma unroll
        for (int r = 0; r < 8; r++) acc[r] = fmaf(s_x[r][k], w, acc[r]);
    }
    for (int r = 0; r < nt; r++)
        g_ep[((size_t)(b * T + t0 + r)) * JOIN + tid] = acc[r];
}

// ---------------- joint: logits = relu(ep + pp) @ Wj2 + bj2, masked ----------------
// grid = B*T/4 (1024), block = 512; thread = (tq = tid>>7, v = tid&127)
__global__ void k_main(const int* __restrict__ es_arr,
                       const int* __restrict__ ts_arr,
                       const float* __restrict__ bj2,
                       float* __restrict__ out) {
    int b  = blockIdx.x >> 7;
    int t0 = (blockIdx.x & 127) << 2;
    int es = es_arr[b], ts = ts_arr[b];
    int tid = threadIdx.x;
    int tq = tid >> 7, v = tid & 127;

    __shared__ float s_ep[4][JOIN];
    __shared__ float s_h[4][JOIN];

    #pragma unroll
    for (int r = 0; r < 4; r++)
        if (t0 + r < es)
            s_ep[r][tid] = g_ep[((size_t)(b * T + t0 + r)) * JOIN + tid];

    float bias = bj2[v];
    bool tvalid = (t0 + tq) < es;
    bool any_t  = t0 < es;

    float* outp = out + ((size_t)(b * T + t0 + tq) * U1) * V + v;
    const float4* wrow = (const float4*)(g_wt + v * JOIN);

    for (int u = 0; u < U1; u++) {
        bool compute = any_t && (u <= ts);
        float val = 0.f;
        if (compute) {
            float ppv = g_pp[(b * U1 + u) * JOIN + tid];
            __syncthreads();   // previous iteration's s_h reads are done
            #pragma unroll
            for (int r = 0; r < 4; r++)
                s_h[r][tid] = fmaxf(s_ep[r][tid] + ppv, 0.f);
            __syncthreads();
            if (tvalid) {      // warp-uniform (tq per warp-group of 4 warps)
                const float4* hrow = (const float4*)(s_h[tq]);
                float acc = bias;
                #pragma unroll 8
                for (int k4 = 0; k4 < JOIN / 4; k4++) {
                    float4 w = wrow[k4];   // L1-resident transposed Wj2 row
                    float4 h = hrow[k4];   // smem broadcast (all lanes same addr)
                    acc = fmaf(h.x, w.x, acc);
                    acc = fmaf(h.y, w.y, acc);
                    acc = fmaf(h.z, w.z, acc);
                    acc = fmaf(h.w, w.w, acc);
                }
                val = acc;
            }
        }
        outp[(size_t)u * V] = val;   // masked positions get exact zeros
    }
}

extern "C" void kernel_launch(void* const* d_in, const int* in_sizes, int n_in,
                              void* d_out, int out_size) {
    const float* enc  = (const float*)d_in[0];
    const int*   es   = (const int*)  d_in[1];
    const void*  tgt  =               d_in[2];   // int64 or int32, auto-detected
    const int*   ts   = (const int*)  d_in[3];
    const float* emb  = (const float*)d_in[4];
    const float* W1   = (const float*)d_in[5];
    const float* b1   = (const float*)d_in[6];
    const float* W2   = (const float*)d_in[7];
    const float* b2   = (const float*)d_in[8];
    const float* Wj1  = (const float*)d_in[9];
    const float* bj1  = (const float*)d_in[10];
    const float* Wj2  = (const float*)d_in[11];
    const float* bj2  = (const float*)d_in[12];
    float* out = (float*)d_out;

    k_wt     <<<(V * JOIN) / 256, 256>>>(Wj2);
    k_pred   <<<B * U1, 512>>>(tgt, emb, W1, b1, W2, b2, Wj1, bj1);
    k_encproj<<<(B * T) / 8, 512>>>(enc, es, Wj1);
    k_main   <<<(B * T) / 4, 512>>>(es, ts, bj2, out);
}

// round 2
// speedup vs baseline: 8.4224x; 8.4224x over previous
#include <cuda_runtime.h>

#define B    8
#define T    512
#define U1   65
#define V    128
#define ENC  512
#define PRED 256
#define JOIN 512
#define NTOK 64
#define NUT  9     // ceil(65/8) u-tiles

// ---- device scratch (no allocations allowed) ----
__device__ float g_pp[B * U1 * JOIN];   // pred_proj + bj1   (1.06 MB)
__device__ float g_ep[B * T * JOIN];    // enc_proj          (8.4 MB)

// ---------------- prediction network + pred_proj (+bj1) ----------------
// grid = B*U1 (520), block = 512
__global__ void k_pred(const void* __restrict__ targets_raw,
                       const float* __restrict__ emb,
                       const float* __restrict__ W1, const float* __restrict__ b1,
                       const float* __restrict__ W2, const float* __restrict__ b2,
                       const float* __restrict__ Wj1, const float* __restrict__ bj1) {
    int b = blockIdx.x / U1;
    int u = blockIdx.x % U1;
    int tid = threadIdx.x;

    __shared__ float s_e[2 * 128];
    __shared__ float s_p[PRED];
    __shared__ float s_q[PRED];
    __shared__ int   s_is64;

    // detect int64 vs int32 targets buffer: if int64, odd 32-bit words
    // (high halves of small nonneg values) are all zero.
    if (tid == 0) {
        const int* w = (const int*)targets_raw;
        int z = 0;
        #pragma unroll
        for (int i = 1; i < 64; i += 2) z |= w[i];
        s_is64 = (z == 0) ? 1 : 0;
    }
    __syncthreads();
    int is64 = s_is64;

    if (tid < 2 * 128) {
        int half = tid >> 7;           // 0 -> targets[u-1], 1 -> targets[u-2]
        int ei   = tid & 127;
        int idx  = u - 1 - half;
        int tok  = V - 1;              // pad token
        if (idx >= 0) {
            if (is64) tok = (int)((const long long*)targets_raw)[b * NTOK + idx];
            else      tok = ((const int*)targets_raw)[b * NTOK + idx];
        }
        s_e[tid] = emb[tok * 128 + ei];
    }
    __syncthreads();

    if (tid < PRED) {
        float acc = b1[tid];
        #pragma unroll 8
        for (int k = 0; k < 2 * 128; k++) acc = fmaf(s_e[k], W1[k * PRED + tid], acc);
        s_p[tid] = fmaxf(acc, 0.f);
    }
    __syncthreads();

    if (tid < PRED) {
        float acc = b2[tid];
        #pragma unroll 8
        for (int k = 0; k < PRED; k++) acc = fmaf(s_p[k], W2[k * PRED + tid], acc);
        s_q[tid] = fmaxf(acc, 0.f);
    }
    __syncthreads();

    // pred_proj[j] = sum_p pred[p] * Wj1[ENC+p][j] + bj1[j]
    {
        float acc = bj1[tid];
        const float* Wp = Wj1 + (size_t)ENC * JOIN;
        #pragma unroll 8
        for (int p = 0; p < PRED; p++) acc = fmaf(s_q[p], Wp[p * JOIN + tid], acc);
        g_pp[(b * U1 + u) * JOIN + tid] = acc;
    }
}

// ---------------- enc_proj: g_ep[b][t][j] = enc[b][t] @ Wj1[:ENC] ----------------
// grid = B*T/8 (512), block = 512, 8 rows register-tiled; skips t >= enc_size
__global__ void k_encproj(const float* __restrict__ enc,
                          const int* __restrict__ es_arr,
                          const float* __restrict__ Wj1) {
    int b  = blockIdx.x >> 6;
    int t0 = (blockIdx.x & 63) << 3;
    int es = es_arr[b];
    if (t0 >= es) return;
    int nt = min(8, es - t0);

    __shared__ float s_x[8][ENC];
    int tid = threadIdx.x;
    for (int r = 0; r < nt; r++)
        s_x[r][tid] = enc[((size_t)(b * T + t0 + r)) * ENC + tid];
    __syncthreads();

    float acc[8] = {0.f, 0.f, 0.f, 0.f, 0.f, 0.f, 0.f, 0.f};
    #pragma unroll 4
    for (int k = 0; k < ENC; k++) {
        float w = Wj1[k * JOIN + tid];
        #pragma unroll
        for (int r = 0; r < 8; r++) acc[r] = fmaf(s_x[r][k], w, acc[r]);
    }
    for (int r = 0; r < nt; r++)
        g_ep[((size_t)(b * T + t0 + r)) * JOIN + tid] = acc[r];
}

// ---------------- joint: smem-tiled GEMM with packed f32x2 FMA ----------------
// Block tile: 64 rows (8 t x 8 u) x 128 cols, K=512 in 16 chunks of 32.
// Even/odd k accumulate in the two f32 lanes of a b64 acc (fma.rn.f32x2);
// reduced at the end. Thread (ty 0..15, tx 0..15): 4 rows x 8 cols.
// grid = B * (T/8) * NUT = 4608, block = 256.
__global__ __launch_bounds__(256, 2)
void k_main(const int* __restrict__ es_arr,
            const int* __restrict__ ts_arr,
            const float* __restrict__ Wj2,
            const float* __restrict__ bj2,
            float* __restrict__ out) {
    int bx = blockIdx.x;
    int b  = bx / (64 * NUT);
    int rm = bx % (64 * NUT);
    int t0 = (rm / NUT) * 8;
    int u0 = (rm % NUT) * 8;
    int es = es_arr[b], ts = ts_arr[b];
    bool docompute = (t0 < es) && (u0 <= ts);   // block-uniform

    int tid = threadIdx.x;
    int ty = tid >> 4, tx = tid & 15;

    __shared__ unsigned long long sA2[16][64];    // [k2][row]  8 KB
    __shared__ unsigned long long sB2[16][128];   // [k2][col] 16 KB
    __shared__ float s_ep[8][33];
    __shared__ float s_pp[8][33];

    unsigned long long acc[4][8];
    #pragma unroll
    for (int i = 0; i < 4; i++)
        #pragma unroll
        for (int j = 0; j < 8; j++) acc[i][j] = 0ULL;

    if (docompute) {
        for (int ch = 0; ch < 16; ch++) {
            int kk = ch * 32;
            __syncthreads();   // previous iteration's smem reads done
            // stage ep / pp chunks (coalesced, 1 elem/thread each)
            {
                int ti = tid >> 5, k = tid & 31;
                s_ep[ti][k] = g_ep[((size_t)(b * T + t0 + ti)) * JOIN + kk + k];
                int uu = u0 + ti; if (uu > U1 - 1) uu = U1 - 1;
                s_pp[ti][k] = g_pp[((size_t)(b * U1 + uu)) * JOIN + kk + k];
            }
            // fill sB2: interleave even/odd k rows of Wj2 (coalesced loads)
            #pragma unroll
            for (int it = 0; it < 8; it++) {
                int idx = it * 256 + tid;
                int k2 = idx >> 7, c = idx & 127;
                float blo = Wj2[(size_t)(kk + 2 * k2)     * V + c];
                float bhi = Wj2[(size_t)(kk + 2 * k2 + 1) * V + c];
                unsigned long long pk;
                asm("mov.b64 %0, {%1,%2};" : "=l"(pk) : "f"(blo), "f"(bhi));
                sB2[k2][c] = pk;
            }
            __syncthreads();
            // build sA2 = relu(ep + pp), k-pair packed
            #pragma unroll
            for (int it = 0; it < 4; it++) {
                int idx = it * 256 + tid;
                int k2 = idx >> 6, r = idx & 63;
                int ti = r & 7, ui = r >> 3;
                float h0 = fmaxf(s_ep[ti][2 * k2]     + s_pp[ui][2 * k2],     0.f);
                float h1 = fmaxf(s_ep[ti][2 * k2 + 1] + s_pp[ui][2 * k2 + 1], 0.f);
                unsigned long long pk;
                asm("mov.b64 %0, {%1,%2};" : "=l"(pk) : "f"(h0), "f"(h1));
                sA2[k2][r] = pk;
            }
            __syncthreads();
            // compute: 16 k2-steps, 6 LDS.128 + 32 FFMA2 each
            #pragma unroll 4
            for (int k2 = 0; k2 < 16; k2++) {
                ulonglong2 a01 = *(const ulonglong2*)&sA2[k2][ty * 4];
                ulonglong2 a23 = *(const ulonglong2*)&sA2[k2][ty * 4 + 2];
                ulonglong2 b01 = *(const ulonglong2*)&sB2[k2][tx * 8];
                ulonglong2 b23 = *(const ulonglong2*)&sB2[k2][tx * 8 + 2];
                ulonglong2 b45 = *(const ulonglong2*)&sB2[k2][tx * 8 + 4];
                ulonglong2 b67 = *(const ulonglong2*)&sB2[k2][tx * 8 + 6];
                unsigned long long av[4] = {a01.x, a01.y, a23.x, a23.y};
                unsigned long long bv[8] = {b01.x, b01.y, b23.x, b23.y,
                                            b45.x, b45.y, b67.x, b67.y};
                #pragma unroll
                for (int i = 0; i < 4; i++)
                    #pragma unroll
                    for (int j = 0; j < 8; j++)
                        asm("fma.rn.f32x2 %0, %1, %2, %0;"
                            : "+l"(acc[i][j]) : "l"(av[i]), "l"(bv[j]));
            }
        }
    }

    // epilogue: reduce lanes, add bias, store (zeros for masked rows)
    float bias[8];
    #pragma unroll
    for (int j = 0; j < 8; j++) bias[j] = bj2[tx * 8 + j];

    #pragma unroll
    for (int rr = 0; rr < 4; rr++) {
        int r = ty * 4 + rr;
        int t = t0 + (r & 7);
        int u = u0 + (r >> 3);
        if (u >= U1) continue;
        bool valid = docompute && (t < es) && (u <= ts);
        float4 v0 = make_float4(0.f, 0.f, 0.f, 0.f);
        float4 v1 = v0;
        if (valid) {
            float vo[8];
            #pragma unroll
            for (int j = 0; j < 8; j++) {
                float lo, hi;
                asm("mov.b64 {%0,%1}, %2;" : "=f"(lo), "=f"(hi) : "l"(acc[rr][j]));
                vo[j] = lo + hi + bias[j];
            }
            v0 = make_float4(vo[0], vo[1], vo[2], vo[3]);
            v1 = make_float4(vo[4], vo[5], vo[6], vo[7]);
        }
        float* p = out + ((size_t)((b * T + t) * U1 + u)) * V + tx * 8;
        *(float4*)p       = v0;
        *(float4*)(p + 4) = v1;
    }
}

extern "C" void kernel_launch(void* const* d_in, const int* in_sizes, int n_in,
                              void* d_out, int out_size) {
    const float* enc  = (const float*)d_in[0];
    const int*   es   = (const int*)  d_in[1];
    const void*  tgt  =               d_in[2];   // int64 or int32, auto-detected
    const int*   ts   = (const int*)  d_in[3];
    const float* emb  = (const float*)d_in[4];
    const float* W1   = (const float*)d_in[5];
    const float* b1   = (const float*)d_in[6];
    const float* W2   = (const float*)d_in[7];
    const float* b2   = (const float*)d_in[8];
    const float* Wj1  = (const float*)d_in[9];
    const float* bj1  = (const float*)d_in[10];
    const float* Wj2  = (const float*)d_in[11];
    const float* bj2  = (const float*)d_in[12];
    float* out = (float*)d_out;

    k_pred   <<<B * U1, 512>>>(tgt, emb, W1, b1, W2, b2, Wj1, bj1);
    k_encproj<<<(B * T) / 8, 512>>>(enc, es, Wj1);
    k_main   <<<B * 64 * NUT, 256>>>(es, ts, Wj2, bj2, out);
}

// round 4
// speedup vs baseline: 20.8216x; 2.4722x over previous
#include <cuda_runtime.h>
#include <cuda_bf16.h>
#include <cstdint>

#define B    8
#define T    512
#define U1   65
#define V    128
#define ENC  512
#define PRED 256
#define JOIN 512
#define NTOK 64

// smem layout for mma kernels (bytes); row stride = 72 bf16 = 144 B (16B-bank safe)
#define OFF_AHI   0
#define OFF_ALO   18432
#define OFF_BHI   36864
#define OFF_BLO   55296
#define OFF_EP    73728
#define OFF_PP    77824
#define OFF_BIAS  79872
#define SMEM_JOINT 80384
#define SMEM_ENC   73728
#define CHUNK_BYTES 36864   // one k64 chunk: hi img (18432) + lo img (18432)

// ---------------- device scratch (no allocations allowed) ----------------
__device__ float g_pp[B * U1 * JOIN];                 // pred_proj + bj1
__device__ float g_ep[B * T * JOIN];                  // enc_proj
__device__ float g_p1[B * U1 * PRED];
__device__ float g_q1[B * U1 * PRED];
__device__ __align__(16) unsigned char g_bt2[8 * CHUNK_BYTES];        // Wj2 images
__device__ __align__(16) unsigned char g_w1t2[4 * 8 * CHUNK_BYTES];   // Wj1[:ENC] images

// ---------------- helpers ----------------
__device__ __forceinline__ uint32_t smem_u32(const void* p) {
    uint32_t a;
    asm("{ .reg .u64 t; cvta.to.shared.u64 t, %1; cvt.u32.u64 %0, t; }" : "=r"(a) : "l"(p));
    return a;
}
__device__ __forceinline__ void ldsm4(uint32_t* r, uint32_t addr) {
    asm volatile("ldmatrix.sync.aligned.m8n8.x4.shared.b16 {%0,%1,%2,%3}, [%4];"
        : "=r"(r[0]), "=r"(r[1]), "=r"(r[2]), "=r"(r[3]) : "r"(addr));
}
__device__ __forceinline__ void mma_bf16(float* c, const uint32_t* a, const uint32_t* b) {
    asm volatile("mma.sync.aligned.m16n8k16.row.col.f32.bf16.bf16.f32 "
        "{%0,%1,%2,%3}, {%4,%5,%6,%7}, {%8,%9}, {%0,%1,%2,%3};"
        : "+f"(c[0]), "+f"(c[1]), "+f"(c[2]), "+f"(c[3])
        : "r"(a[0]), "r"(a[1]), "r"(a[2]), "r"(a[3]), "r"(b[0]), "r"(b[1]));
}

// ---------------- k_prep: build padded bf16 hi/lo weight images ----------------
// layout per chunk c (k 64): hi[n][72] then lo[n][72], bf16
__global__ void k_prep(const float* __restrict__ Wj1, const float* __restrict__ Wj2) {
    int idx = blockIdx.x * 256 + threadIdx.x;
    if (idx < 65536) {
        int k = idx >> 7, n = idx & 127;
        float w = Wj2[idx];
        __nv_bfloat16 hi = __float2bfloat16(w);
        __nv_bfloat16 lo = __float2bfloat16(w - __bfloat162float(hi));
        size_t base = (size_t)(k >> 6) * CHUNK_BYTES + (size_t)n * 144 + (k & 63) * 2;
        *(__nv_bfloat16*)(g_bt2 + base)         = hi;
        *(__nv_bfloat16*)(g_bt2 + base + 18432) = lo;
    } else {
        int j = idx - 65536;
        if (j >= 262144) return;
        int k = j >> 9, n = j & 511;
        float w = Wj1[(size_t)k * JOIN + n];
        __nv_bfloat16 hi = __float2bfloat16(w);
        __nv_bfloat16 lo = __float2bfloat16(w - __bfloat162float(hi));
        size_t base = (size_t)((n >> 7) * 8 + (k >> 6)) * CHUNK_BYTES
                    + (size_t)(n & 127) * 144 + (k & 63) * 2;
        *(__nv_bfloat16*)(g_w1t2 + base)         = hi;
        *(__nv_bfloat16*)(g_w1t2 + base + 18432) = lo;
    }
}

// ---------------- prediction net: 3 row-tiled FFMA kernels ----------------
__global__ void kp1(const void* __restrict__ targets_raw,
                    const float* __restrict__ emb,
                    const float* __restrict__ W1, const float* __restrict__ b1) {
    int r0 = blockIdx.x * 8;
    int tid = threadIdx.x;
    __shared__ float s_e[8][256];
    __shared__ int s_is64;
    if (tid == 0) {
        const int* w = (const int*)targets_raw;
        int z = 0;
        #pragma unroll
        for (int i = 1; i < 64; i += 2) z |= w[i];
        s_is64 = (z == 0) ? 1 : 0;
    }
    __syncthreads();
    int is64 = s_is64;
    #pragma unroll
    for (int rr = 0; rr < 8; rr++) {
        int row = r0 + rr;
        int b = row / U1, u = row % U1;
        int half = tid >> 7;
        int idx = u - 1 - half;
        int tok = V - 1;
        if (idx >= 0) {
            if (is64) tok = (int)((const long long*)targets_raw)[b * NTOK + idx];
            else      tok = ((const int*)targets_raw)[b * NTOK + idx];
        }
        s_e[rr][tid] = emb[tok * 128 + (tid & 127)];
    }
    __syncthreads();
    float acc[8];
    #pragma unroll
    for (int j = 0; j < 8; j++) acc[j] = b1[tid];
    #pragma unroll 4
    for (int k = 0; k < 256; k++) {
        float w = W1[k * PRED + tid];
        #pragma unroll
        for (int j = 0; j < 8; j++) acc[j] = fmaf(s_e[j][k], w, acc[j]);
    }
    #pragma unroll
    for (int j = 0; j < 8; j++) g_p1[(r0 + j) * PRED + tid] = fmaxf(acc[j], 0.f);
}

__global__ void kp2(const float* __restrict__ W2, const float* __restrict__ b2) {
    int r0 = blockIdx.x * 8;
    int tid = threadIdx.x;
    __shared__ float s_p[8][256];
    #pragma unroll
    for (int rr = 0; rr < 8; rr++) s_p[rr][tid] = g_p1[(r0 + rr) * PRED + tid];
    __syncthreads();
    float acc[8];
    #pragma unroll
    for (int j = 0; j < 8; j++) acc[j] = b2[tid];
    #pragma unroll 4
    for (int k = 0; k < 256; k++) {
        float w = W2[k * PRED + tid];
        #pragma unroll
        for (int j = 0; j < 8; j++) acc[j] = fmaf(s_p[j][k], w, acc[j]);
    }
    #pragma unroll
    for (int j = 0; j < 8; j++) g_q1[(r0 + j) * PRED + tid] = fmaxf(acc[j], 0.f);
}

__global__ void kp3(const float* __restrict__ Wj1, const float* __restrict__ bj1) {
    int r0 = blockIdx.x * 8;
    int tid = threadIdx.x;   // 512 threads
    __shared__ float s_q[8][256];
    #pragma unroll
    for (int i = 0; i < 4; i++) {
        int idx = i * 512 + tid;
        s_q[idx >> 8][idx & 255] = g_q1[(r0 + (idx >> 8)) * PRED + (idx & 255)];
    }
    __syncthreads();
    float acc[8];
    #pragma unroll
    for (int j = 0; j < 8; j++) acc[j] = bj1[tid];
    const float* Wp = Wj1 + (size_t)ENC * JOIN;
    #pragma unroll 4
    for (int k = 0; k < 256; k++) {
        float w = Wp[k * JOIN + tid];
        #pragma unroll
        for (int j = 0; j < 8; j++) acc[j] = fmaf(s_q[j][k], w, acc[j]);
    }
    #pragma unroll
    for (int j = 0; j < 8; j++) g_pp[(size_t)(r0 + j) * JOIN + tid] = acc[j];
}

// ---------------- enc_proj via mma.sync ----------------
// grid = 8 b * 4 t-tiles * 4 n-tiles = 128, block = 256 (8 warps: 4m x 2n)
__global__ __launch_bounds__(256, 2)
void k_enc(const float* __restrict__ enc, const int* __restrict__ es_arr) {
    extern __shared__ char sm[];
    int bx = blockIdx.x;
    int b = bx >> 4, tt = (bx >> 2) & 3, nt = bx & 3;
    int t0 = tt * 128;
    if (t0 >= es_arr[b]) return;
    int tid = threadIdx.x, lane = tid & 31, wid = tid >> 5;
    int wm = wid & 3, wn = wid >> 2;
    uint32_t sb = smem_u32(sm);

    uint32_t aoff = (uint32_t)(wm * 32 + (lane & 15)) * 144 + ((lane >> 4) << 4);
    uint32_t a_hi = sb + OFF_AHI + aoff, a_lo = sb + OFF_ALO + aoff;
    uint32_t boff = (uint32_t)(wn * 64 + (lane & 7) + ((lane >> 4) << 3)) * 144
                  + (((lane >> 3) & 1) << 4);
    uint32_t b_hi = sb + OFF_BHI + boff, b_lo = sb + OFF_BLO + boff;

    float acc[2][8][4];
    #pragma unroll
    for (int i = 0; i < 2; i++)
        #pragma unroll
        for (int j = 0; j < 8; j++)
            #pragma unroll
            for (int q = 0; q < 4; q++) acc[i][j][q] = 0.f;

    for (int c = 0; c < 8; c++) {
        // copy B images (36864 B)
        {
            const uint4* src = (const uint4*)(g_w1t2 + (size_t)(nt * 8 + c) * CHUNK_BYTES);
            uint4* dst = (uint4*)(sm + OFF_BHI);
            #pragma unroll
            for (int i = 0; i < 9; i++) dst[i * 256 + tid] = src[i * 256 + tid];
        }
        // build A images from enc
        #pragma unroll
        for (int i = 0; i < 16; i++) {
            int p = i * 256 + tid;
            int row = p >> 5, kp = p & 31;
            float2 e = *(const float2*)&enc[((size_t)(b * T + t0 + row)) * ENC + c * 64 + 2 * kp];
            __nv_bfloat162 hp = __floats2bfloat162_rn(e.x, e.y);
            float2 hf = __bfloat1622float2(hp);
            __nv_bfloat162 lp = __floats2bfloat162_rn(e.x - hf.x, e.y - hf.y);
            uint32_t ad = (uint32_t)row * 144 + kp * 4;
            *(__nv_bfloat162*)(sm + OFF_AHI + ad) = hp;
            *(__nv_bfloat162*)(sm + OFF_ALO + ad) = lp;
        }
        __syncthreads();
        #pragma unroll
        for (int s = 0; s < 4; s++) {
            uint32_t bh[16], bl[16];
            #pragma unroll
            for (int j2 = 0; j2 < 4; j2++) {
                ldsm4(&bh[j2 * 4], b_hi + j2 * 16 * 144 + s * 32);
                ldsm4(&bl[j2 * 4], b_lo + j2 * 16 * 144 + s * 32);
            }
            #pragma unroll
            for (int mi = 0; mi < 2; mi++) {
                uint32_t ah[4], al[4];
                ldsm4(ah, a_hi + mi * 16 * 144 + s * 32);
                ldsm4(al, a_lo + mi * 16 * 144 + s * 32);
                #pragma unroll
                for (int nj = 0; nj < 8; nj++) {
                    mma_bf16(acc[mi][nj], ah, &bh[nj * 2]);
                    mma_bf16(acc[mi][nj], ah, &bl[nj * 2]);
                    mma_bf16(acc[mi][nj], al, &bh[nj * 2]);
                }
            }
        }
        __syncthreads();
    }
    int gid = lane >> 2, tig = lane & 3;
    #pragma unroll
    for (int mi = 0; mi < 2; mi++)
        #pragma unroll
        for (int nj = 0; nj < 8; nj++) {
            int col = nt * 128 + wn * 64 + nj * 8 + tig * 2;
            #pragma unroll
            for (int hh = 0; hh < 2; hh++) {
                int row = wm * 32 + mi * 16 + gid + hh * 8;
                int t = t0 + row;
                *(float2*)&g_ep[((size_t)(b * T + t)) * JOIN + col] =
                    make_float2(acc[mi][nj][hh * 2], acc[mi][nj][hh * 2 + 1]);
            }
        }
}

// ---------------- joint via mma.sync ----------------
// tile = 128 rows (16 t x 8 u) x 128 v, K=512. grid = 8*32*9 = 2304, block = 256
__global__ __launch_bounds__(256, 2)
void k_joint(const int* __restrict__ es_arr, const int* __restrict__ ts_arr,
             const float* __restrict__ bj2, float* __restrict__ out) {
    extern __shared__ char sm[];
    int bx = blockIdx.x;
    int b = bx / 288, rem = bx % 288;
    int t0 = (rem / 9) * 16, u0 = (rem % 9) * 8;
    int es = es_arr[b], ts = ts_arr[b];
    int tid = threadIdx.x;
    bool live = (t0 < es) && (u0 <= ts);

    if (!live) {
        float4 z = make_float4(0.f, 0.f, 0.f, 0.f);
        #pragma unroll
        for (int i = 0; i < 16; i++) {
            int f4 = i * 256 + tid;
            int row = f4 >> 5, c4 = f4 & 31;
            int t = t0 + (row >> 3), u = u0 + (row & 7);
            if (u < U1)
                *(float4*)(out + (((size_t)(b * T + t) * U1 + u) << 7) + c4 * 4) = z;
        }
        return;
    }

    int lane = tid & 31, wid = tid >> 5;
    int wm = wid & 3, wn = wid >> 2;
    uint32_t sb = smem_u32(sm);
    float* s_ep   = (float*)(sm + OFF_EP);
    float* s_pp   = (float*)(sm + OFF_PP);
    float* s_bias = (float*)(sm + OFF_BIAS);
    if (tid < 128) s_bias[tid] = bj2[tid];

    uint32_t aoff = (uint32_t)(wm * 32 + (lane & 15)) * 144 + ((lane >> 4) << 4);
    uint32_t a_hi = sb + OFF_AHI + aoff, a_lo = sb + OFF_ALO + aoff;
    uint32_t boff = (uint32_t)(wn * 64 + (lane & 7) + ((lane >> 4) << 3)) * 144
                  + (((lane >> 3) & 1) << 4);
    uint32_t b_hi = sb + OFF_BHI + boff, b_lo = sb + OFF_BLO + boff;

    float acc[2][8][4];
    #pragma unroll
    for (int i = 0; i < 2; i++)
        #pragma unroll
        for (int j = 0; j < 8; j++)
            #pragma unroll
            for (int q = 0; q < 4; q++) acc[i][j][q] = 0.f;

    for (int c = 0; c < 8; c++) {
        // stage ep / pp chunk (coalesced float4)
        {
            int ti = tid >> 4, c4 = tid & 15;
            *(float4*)&s_ep[ti * 64 + c4 * 4] =
                *(const float4*)&g_ep[((size_t)(b * T + t0 + ti)) * JOIN + c * 64 + c4 * 4];
            if (tid < 128) {
                int ui = tid >> 4, c42 = tid & 15;
                int uu = u0 + ui; if (uu > 64) uu = 64;
                *(float4*)&s_pp[ui * 64 + c42 * 4] =
                    *(const float4*)&g_pp[((size_t)(b * U1 + uu)) * JOIN + c * 64 + c42 * 4];
            }
        }
        // copy B images (36864 B)
        {
            const uint4* src = (const uint4*)(g_bt2 + (size_t)c * CHUNK_BYTES);
            uint4* dst = (uint4*)(sm + OFF_BHI);
            #pragma unroll
            for (int i = 0; i < 9; i++) dst[i * 256 + tid] = src[i * 256 + tid];
        }
        __syncthreads();
        // build A = relu(ep + pp), bf16 hi/lo
        #pragma unroll
        for (int i = 0; i < 16; i++) {
            int p = i * 256 + tid;
            int row = p >> 5, kp = p & 31;
            int ti = row >> 3, ui = row & 7;
            float2 e = *(const float2*)&s_ep[ti * 64 + 2 * kp];
            float2 q = *(const float2*)&s_pp[ui * 64 + 2 * kp];
            float h0 = fmaxf(e.x + q.x, 0.f), h1 = fmaxf(e.y + q.y, 0.f);
            __nv_bfloat162 hp = __floats2bfloat162_rn(h0, h1);
            float2 hf = __bfloat1622float2(hp);
            __nv_bfloat162 lp = __floats2bfloat162_rn(h0 - hf.x, h1 - hf.y);
            uint32_t ad = (uint32_t)row * 144 + kp * 4;
            *(__nv_bfloat162*)(sm + OFF_AHI + ad) = hp;
            *(__nv_bfloat162*)(sm + OFF_ALO + ad) = lp;
        }
        __syncthreads();
        #pragma unroll
        for (int s = 0; s < 4; s++) {
            uint32_t bh[16], bl[16];
            #pragma unroll
            for (int j2 = 0; j2 < 4; j2++) {
                ldsm4(&bh[j2 * 4], b_hi + j2 * 16 * 144 + s * 32);
                ldsm4(&bl[j2 * 4], b_lo + j2 * 16 * 144 + s * 32);
            }
            #pragma unroll
            for (int mi = 0; mi < 2; mi++) {
                uint32_t ah[4], al[4];
                ldsm4(ah, a_hi + mi * 16 * 144 + s * 32);
                ldsm4(al, a_lo + mi * 16 * 144 + s * 32);
                #pragma unroll
                for (int nj = 0; nj < 8; nj++) {
                    mma_bf16(acc[mi][nj], ah, &bh[nj * 2]);
                    mma_bf16(acc[mi][nj], ah, &bl[nj * 2]);
                    mma_bf16(acc[mi][nj], al, &bh[nj * 2]);
                }
            }
        }
        __syncthreads();
    }

    // epilogue: bias + mask + store
    int gid = lane >> 2, tig = lane & 3;
    #pragma unroll
    for (int mi = 0; mi < 2; mi++)
        #pragma unroll
        for (int nj = 0; nj < 8; nj++) {
            int col = wn * 64 + nj * 8 + tig * 2;
            float b0f = s_bias[col], b1f = s_bias[col + 1];
            #pragma unroll
            for (int hh = 0; hh < 2; hh++) {
                int row = wm * 32 + mi * 16 + gid + hh * 8;
                int t = t0 + (row >> 3), u = u0 + (row & 7);
                if (u >= U1) continue;
                bool valid = (t < es) && (u <= ts);
                float v0 = valid ? acc[mi][nj][hh * 2]     + b0f : 0.f;
                float v1 = valid ? acc[mi][nj][hh * 2 + 1] + b1f : 0.f;
                *(float2*)(out + (((size_t)(b * T + t) * U1 + u) << 7) + col) =
                    make_float2(v0, v1);
            }
        }
}

extern "C" void kernel_launch(void* const* d_in, const int* in_sizes, int n_in,
                              void* d_out, int out_size) {
    const float* enc  = (const float*)d_in[0];
    const int*   es   = (const int*)  d_in[1];
    const void*  tgt  =               d_in[2];   // int64 or int32, auto-detected
    const int*   ts   = (const int*)  d_in[3];
    const float* emb  = (const float*)d_in[4];
    const float* W1   = (const float*)d_in[5];
    const float* b1   = (const float*)d_in[6];
    const float* W2   = (const float*)d_in[7];
    const float* b2   = (const float*)d_in[8];
    const float* Wj1  = (const float*)d_in[9];
    const float* bj1  = (const float*)d_in[10];
    const float* Wj2  = (const float*)d_in[11];
    const float* bj2  = (const float*)d_in[12];
    float* out = (float*)d_out;

    static bool attr_done = false;
    if (!attr_done) {
        cudaFuncSetAttribute(k_enc,   cudaFuncAttributeMaxDynamicSharedMemorySize, SMEM_ENC);
        cudaFuncSetAttribute(k_joint, cudaFuncAttributeMaxDynamicSharedMemorySize, SMEM_JOINT);
        attr_done = true;
    }

    k_prep<<<1280, 256>>>(Wj1, Wj2);
    kp1   <<<65, 256>>>(tgt, emb, W1, b1);
    kp2   <<<65, 256>>>(W2, b2);
    kp3   <<<65, 512>>>(Wj1, bj1);
    k_enc <<<128, 256, SMEM_ENC>>>(enc, es);
    k_joint<<<2304, 256, SMEM_JOINT>>>(es, ts, bj2, out);
}

// round 5
// speedup vs baseline: 29.4960x; 1.4166x over previous
#include <cuda_runtime.h>
#include <cuda_bf16.h>
#include <cstdint>

#define B    8
#define T    512
#define U1   65
#define V    128
#define ENC  512
#define PRED 256
#define JOIN 512
#define NTOK 64

// smem layout for mma kernels (bytes); row stride = 72 bf16 = 144 B
#define OFF_AHI   0
#define OFF_ALO   18432
#define OFF_BHI   36864
#define OFF_BLO   55296
#define OFF_EP    73728
#define OFF_PP    77824
#define OFF_BIAS  79872
#define SMEM_JOINT 80384
#define SMEM_ALL   73728
#define CHUNK_BYTES 36864   // one k64 chunk: hi img (18432) + lo img (18432)

// ---------------- device scratch (no allocations allowed) ----------------
__device__ float g_pp[B * U1 * JOIN];                 // pred_proj + bj1
__device__ float g_ep[B * T * JOIN];                  // enc_proj
__device__ __align__(16) unsigned char g_bt2[8 * CHUNK_BYTES];   // Wj2 images

// ---------------- helpers ----------------
__device__ __forceinline__ uint32_t smem_u32(const void* p) {
    uint32_t a;
    asm("{ .reg .u64 t; cvta.to.shared.u64 t, %1; cvt.u32.u64 %0, t; }" : "=r"(a) : "l"(p));
    return a;
}
__device__ __forceinline__ void ldsm4(uint32_t* r, uint32_t addr) {
    asm volatile("ldmatrix.sync.aligned.m8n8.x4.shared.b16 {%0,%1,%2,%3}, [%4];"
        : "=r"(r[0]), "=r"(r[1]), "=r"(r[2]), "=r"(r[3]) : "r"(addr));
}
__device__ __forceinline__ void mma_bf16(float* c, const uint32_t* a, const uint32_t* b) {
    asm volatile("mma.sync.aligned.m16n8k16.row.col.f32.bf16.bf16.f32 "
        "{%0,%1,%2,%3}, {%4,%5,%6,%7}, {%8,%9}, {%0,%1,%2,%3};"
        : "+f"(c[0]), "+f"(c[1]), "+f"(c[2]), "+f"(c[3])
        : "r"(a[0]), "r"(a[1]), "r"(a[2]), "r"(a[3]), "r"(b[0]), "r"(b[1]));
}

// ======================================================================
// k_all: role-split fused kernel.
//   blocks   0..127 : enc_proj MMA (self-converting Wj1 B-tiles)
//   blocks 128..192 : fused prediction net (8 rows/block)
//   blocks 193..256 : Wj2 bf16 hi/lo image prep for k_joint
// ======================================================================
__global__ __launch_bounds__(256, 2)
void k_all(const float* __restrict__ enc, const int* __restrict__ es_arr,
           const void* __restrict__ targets_raw,
           const float* __restrict__ emb,
           const float* __restrict__ W1, const float* __restrict__ b1,
           const float* __restrict__ W2, const float* __restrict__ b2,
           const float* __restrict__ Wj1, const float* __restrict__ bj1,
           const float* __restrict__ Wj2) {
    extern __shared__ char sm[];
    int bx = blockIdx.x;
    int tid = threadIdx.x;

    if (bx >= 193) {
        // ---------------- prep role: Wj2 -> bf16 hi/lo images ----------------
        int base_i = (bx - 193) * 1024;
        #pragma unroll
        for (int i = 0; i < 4; i++) {
            int idx = base_i + i * 256 + tid;       // < 65536
            int k = idx >> 7, n = idx & 127;
            float w = Wj2[idx];
            __nv_bfloat16 hi = __float2bfloat16(w);
            __nv_bfloat16 lo = __float2bfloat16(w - __bfloat162float(hi));
            size_t dst = (size_t)(k >> 6) * CHUNK_BYTES + (size_t)n * 144 + (k & 63) * 2;
            *(__nv_bfloat16*)(g_bt2 + dst)         = hi;
            *(__nv_bfloat16*)(g_bt2 + dst + 18432) = lo;
        }
        return;
    }

    if (bx >= 128) {
        // ---------------- pred role: fused embed -> W1 -> W2 -> Wp ----------------
        float* s_e = (float*)sm;                 // [8][256]
        float* s_p = s_e + 8 * 256;              // [8][256]
        float* s_q = s_p + 8 * 256;              // [8][256]
        __shared__ int s_is64;
        int r0 = (bx - 128) * 8;

        if (tid == 0) {
            const int* w = (const int*)targets_raw;
            int z = 0;
            #pragma unroll
            for (int i = 1; i < 64; i += 2) z |= w[i];
            s_is64 = (z == 0) ? 1 : 0;
        }
        __syncthreads();
        int is64 = s_is64;

        // embedding gather: 2048 elems, 8 per thread
        #pragma unroll
        for (int i = 0; i < 8; i++) {
            int idx = i * 256 + tid;
            int rr = idx >> 8, rest = idx & 255;
            int half = rest >> 7, ei = rest & 127;
            int row = r0 + rr;
            int b = row / U1, u = row % U1;
            int tix = u - 1 - half;
            int tok = V - 1;
            if (tix >= 0) {
                if (is64) tok = (int)((const long long*)targets_raw)[b * NTOK + tix];
                else      tok = ((const int*)targets_raw)[b * NTOK + tix];
            }
            s_e[rr * 256 + half * 128 + ei] = emb[tok * 128 + ei];
        }
        __syncthreads();

        // stage 1
        {
            float acc[8];
            float bb = b1[tid];
            #pragma unroll
            for (int r = 0; r < 8; r++) acc[r] = bb;
            #pragma unroll 8
            for (int k = 0; k < 256; k++) {
                float w = W1[k * PRED + tid];
                #pragma unroll
                for (int r = 0; r < 8; r++) acc[r] = fmaf(s_e[r * 256 + k], w, acc[r]);
            }
            #pragma unroll
            for (int r = 0; r < 8; r++) s_p[r * 256 + tid] = fmaxf(acc[r], 0.f);
        }
        __syncthreads();

        // stage 2
        {
            float acc[8];
            float bb = b2[tid];
            #pragma unroll
            for (int r = 0; r < 8; r++) acc[r] = bb;
            #pragma unroll 8
            for (int k = 0; k < 256; k++) {
                float w = W2[k * PRED + tid];
                #pragma unroll
                for (int r = 0; r < 8; r++) acc[r] = fmaf(s_p[r * 256 + k], w, acc[r]);
            }
            #pragma unroll
            for (int r = 0; r < 8; r++) s_q[r * 256 + tid] = fmaxf(acc[r], 0.f);
        }
        __syncthreads();

        // stage 3: pred @ Wp + bj1 -> g_pp ; cols tid and tid+256
        {
            float acc0[8], acc1[8];
            float bb0 = bj1[tid], bb1 = bj1[tid + 256];
            #pragma unroll
            for (int r = 0; r < 8; r++) { acc0[r] = bb0; acc1[r] = bb1; }
            const float* Wp = Wj1 + (size_t)ENC * JOIN;
            #pragma unroll 4
            for (int k = 0; k < 256; k++) {
                float w0 = Wp[k * JOIN + tid];
                float w1 = Wp[k * JOIN + tid + 256];
                #pragma unroll
                for (int r = 0; r < 8; r++) {
                    float q = s_q[r * 256 + k];
                    acc0[r] = fmaf(q, w0, acc0[r]);
                    acc1[r] = fmaf(q, w1, acc1[r]);
                }
            }
            #pragma unroll
            for (int r = 0; r < 8; r++) {
                g_pp[(size_t)(r0 + r) * JOIN + tid]       = acc0[r];
                g_pp[(size_t)(r0 + r) * JOIN + tid + 256] = acc1[r];
            }
        }
        return;
    }

    // ---------------- enc role: g_ep tile via mma.sync, self-converted B ----------------
    {
        int b = bx >> 4, tt = (bx >> 2) & 3, nt = bx & 3;
        int t0 = tt * 128;
        if (t0 >= es_arr[b]) return;
        int lane = tid & 31, wid = tid >> 5;
        int wm = wid & 3, wn = wid >> 2;
        uint32_t sb = smem_u32(sm);

        uint32_t aoff = (uint32_t)(wm * 32 + (lane & 15)) * 144 + ((lane >> 4) << 4);
        uint32_t a_hi = sb + OFF_AHI + aoff, a_lo = sb + OFF_ALO + aoff;
        uint32_t boff = (uint32_t)(wn * 64 + (lane & 7) + ((lane >> 4) << 3)) * 144
                      + (((lane >> 3) & 1) << 4);
        uint32_t b_hi = sb + OFF_BHI + boff, b_lo = sb + OFF_BLO + boff;

        float acc[2][8][4];
        #pragma unroll
        for (int i = 0; i < 2; i++)
            #pragma unroll
            for (int j = 0; j < 8; j++)
                #pragma unroll
                for (int q = 0; q < 4; q++) acc[i][j][q] = 0.f;

        float* s_stage = (float*)(sm + OFF_AHI);   // [64][129] floats, aliased on A region

        for (int c = 0; c < 8; c++) {
            // 1) stage Wj1 float tile (coalesced)
            #pragma unroll
            for (int i = 0; i < 32; i++) {
                int idx = i * 256 + tid;
                int kk = idx >> 7, nn = idx & 127;
                s_stage[kk * 129 + nn] =
                    Wj1[(size_t)(c * 64 + kk) * JOIN + nt * 128 + nn];
            }
            __syncthreads();
            // 2) convert -> B bf16 hi/lo images
            #pragma unroll
            for (int i = 0; i < 16; i++) {
                int p = i * 256 + tid;
                int n = p >> 5, kp = p & 31;
                float f0 = s_stage[(2 * kp) * 129 + n];
                float f1 = s_stage[(2 * kp + 1) * 129 + n];
                __nv_bfloat162 hp = __floats2bfloat162_rn(f0, f1);
                float2 hf = __bfloat1622float2(hp);
                __nv_bfloat162 lp = __floats2bfloat162_rn(f0 - hf.x, f1 - hf.y);
                uint32_t ad = (uint32_t)n * 144 + kp * 4;
                *(__nv_bfloat162*)(sm + OFF_BHI + ad) = hp;
                *(__nv_bfloat162*)(sm + OFF_BLO + ad) = lp;
            }
            __syncthreads();
            // 3) build A images from enc (overwrites stage region)
            #pragma unroll
            for (int i = 0; i < 16; i++) {
                int p = i * 256 + tid;
                int row = p >> 5, kp = p & 31;
                float2 e = *(const float2*)&enc[((size_t)(b * T + t0 + row)) * ENC + c * 64 + 2 * kp];
                __nv_bfloat162 hp = __floats2bfloat162_rn(e.x, e.y);
                float2 hf = __bfloat1622float2(hp);
                __nv_bfloat162 lp = __floats2bfloat162_rn(e.x - hf.x, e.y - hf.y);
                uint32_t ad = (uint32_t)row * 144 + kp * 4;
                *(__nv_bfloat162*)(sm + OFF_AHI + ad) = hp;
                *(__nv_bfloat162*)(sm + OFF_ALO + ad) = lp;
            }
            __syncthreads();
            // 4) ldmatrix + mma
            #pragma unroll
            for (int s = 0; s < 4; s++) {
                uint32_t bh[16], bl[16];
                #pragma unroll
                for (int j2 = 0; j2 < 4; j2++) {
                    ldsm4(&bh[j2 * 4], b_hi + j2 * 16 * 144 + s * 32);
                    ldsm4(&bl[j2 * 4], b_lo + j2 * 16 * 144 + s * 32);
                }
                #pragma unroll
                for (int mi = 0; mi < 2; mi++) {
                    uint32_t ah[4], al[4];
                    ldsm4(ah, a_hi + mi * 16 * 144 + s * 32);
                    ldsm4(al, a_lo + mi * 16 * 144 + s * 32);
                    #pragma unroll
                    for (int nj = 0; nj < 8; nj++) {
                        mma_bf16(acc[mi][nj], ah, &bh[nj * 2]);
                        mma_bf16(acc[mi][nj], ah, &bl[nj * 2]);
                        mma_bf16(acc[mi][nj], al, &bh[nj * 2]);
                    }
                }
            }
            __syncthreads();
        }
        int gid = lane >> 2, tig = lane & 3;
        #pragma unroll
        for (int mi = 0; mi < 2; mi++)
            #pragma unroll
            for (int nj = 0; nj < 8; nj++) {
                int col = nt * 128 + wn * 64 + nj * 8 + tig * 2;
                #pragma unroll
                for (int hh = 0; hh < 2; hh++) {
                    int row = wm * 32 + mi * 16 + gid + hh * 8;
                    int t = t0 + row;
                    *(float2*)&g_ep[((size_t)(b * T + t)) * JOIN + col] =
                        make_float2(acc[mi][nj][hh * 2], acc[mi][nj][hh * 2 + 1]);
                }
            }
    }
}

// ---------------- joint via mma.sync (unchanged from R4) ----------------
__global__ __launch_bounds__(256, 2)
void k_joint(const int* __restrict__ es_arr, const int* __restrict__ ts_arr,
             const float* __restrict__ bj2, float* __restrict__ out) {
    extern __shared__ char sm[];
    int bx = blockIdx.x;
    int b = bx / 288, rem = bx % 288;
    int t0 = (rem / 9) * 16, u0 = (rem % 9) * 8;
    int es = es_arr[b], ts = ts_arr[b];
    int tid = threadIdx.x;
    bool live = (t0 < es) && (u0 <= ts);

    if (!live) {
        float4 z = make_float4(0.f, 0.f, 0.f, 0.f);
        #pragma unroll
        for (int i = 0; i < 16; i++) {
            int f4 = i * 256 + tid;
            int row = f4 >> 5, c4 = f4 & 31;
            int t = t0 + (row >> 3), u = u0 + (row & 7);
            if (u < U1)
                *(float4*)(out + (((size_t)(b * T + t) * U1 + u) << 7) + c4 * 4) = z;
        }
        return;
    }

    int lane = tid & 31, wid = tid >> 5;
    int wm = wid & 3, wn = wid >> 2;
    uint32_t sb = smem_u32(sm);
    float* s_ep   = (float*)(sm + OFF_EP);
    float* s_pp   = (float*)(sm + OFF_PP);
    float* s_bias = (float*)(sm + OFF_BIAS);
    if (tid < 128) s_bias[tid] = bj2[tid];

    uint32_t aoff = (uint32_t)(wm * 32 + (lane & 15)) * 144 + ((lane >> 4) << 4);
    uint32_t a_hi = sb + OFF_AHI + aoff, a_lo = sb + OFF_ALO + aoff;
    uint32_t boff = (uint32_t)(wn * 64 + (lane & 7) + ((lane >> 4) << 3)) * 144
                  + (((lane >> 3) & 1) << 4);
    uint32_t b_hi = sb + OFF_BHI + boff, b_lo = sb + OFF_BLO + boff;

    float acc[2][8][4];
    #pragma unroll
    for (int i = 0; i < 2; i++)
        #pragma unroll
        for (int j = 0; j < 8; j++)
            #pragma unroll
            for (int q = 0; q < 4; q++) acc[i][j][q] = 0.f;

    for (int c = 0; c < 8; c++) {
        {
            int ti = tid >> 4, c4 = tid & 15;
            *(float4*)&s_ep[ti * 64 + c4 * 4] =
                *(const float4*)&g_ep[((size_t)(b * T + t0 + ti)) * JOIN + c * 64 + c4 * 4];
            if (tid < 128) {
                int ui = tid >> 4, c42 = tid & 15;
                int uu = u0 + ui; if (uu > 64) uu = 64;
                *(float4*)&s_pp[ui * 64 + c42 * 4] =
                    *(const float4*)&g_pp[((size_t)(b * U1 + uu)) * JOIN + c * 64 + c42 * 4];
            }
        }
        {
            const uint4* src = (const uint4*)(g_bt2 + (size_t)c * CHUNK_BYTES);
            uint4* dst = (uint4*)(sm + OFF_BHI);
            #pragma unroll
            for (int i = 0; i < 9; i++) dst[i * 256 + tid] = src[i * 256 + tid];
        }
        __syncthreads();
        #pragma unroll
        for (int i = 0; i < 16; i++) {
            int p = i * 256 + tid;
            int row = p >> 5, kp = p & 31;
            int ti = row >> 3, ui = row & 7;
            float2 e = *(const float2*)&s_ep[ti * 64 + 2 * kp];
            float2 q = *(const float2*)&s_pp[ui * 64 + 2 * kp];
            float h0 = fmaxf(e.x + q.x, 0.f), h1 = fmaxf(e.y + q.y, 0.f);
            __nv_bfloat162 hp = __floats2bfloat162_rn(h0, h1);
            float2 hf = __bfloat1622float2(hp);
            __nv_bfloat162 lp = __floats2bfloat162_rn(h0 - hf.x, h1 - hf.y);
            uint32_t ad = (uint32_t)row * 144 + kp * 4;
            *(__nv_bfloat162*)(sm + OFF_AHI + ad) = hp;
            *(__nv_bfloat162*)(sm + OFF_ALO + ad) = lp;
        }
        __syncthreads();
        #pragma unroll
        for (int s = 0; s < 4; s++) {
            uint32_t bh[16], bl[16];
            #pragma unroll
            for (int j2 = 0; j2 < 4; j2++) {
                ldsm4(&bh[j2 * 4], b_hi + j2 * 16 * 144 + s * 32);
                ldsm4(&bl[j2 * 4], b_lo + j2 * 16 * 144 + s * 32);
            }
            #pragma unroll
            for (int mi = 0; mi < 2; mi++) {
                uint32_t ah[4], al[4];
                ldsm4(ah, a_hi + mi * 16 * 144 + s * 32);
                ldsm4(al, a_lo + mi * 16 * 144 + s * 32);
                #pragma unroll
                for (int nj = 0; nj < 8; nj++) {
                    mma_bf16(acc[mi][nj], ah, &bh[nj * 2]);
                    mma_bf16(acc[mi][nj], ah, &bl[nj * 2]);
                    mma_bf16(acc[mi][nj], al, &bh[nj * 2]);
                }
            }
        }
        __syncthreads();
    }

    int gid = lane >> 2, tig = lane & 3;
    #pragma unroll
    for (int mi = 0; mi < 2; mi++)
        #pragma unroll
        for (int nj = 0; nj < 8; nj++) {
            int col = wn * 64 + nj * 8 + tig * 2;
            float b0f = s_bias[col], b1f = s_bias[col + 1];
            #pragma unroll
            for (int hh = 0; hh < 2; hh++) {
                int row = wm * 32 + mi * 16 + gid + hh * 8;
                int t = t0 + (row >> 3), u = u0 + (row & 7);
                if (u >= U1) continue;
                bool valid = (t < es) && (u <= ts);
                float v0 = valid ? acc[mi][nj][hh * 2]     + b0f : 0.f;
                float v1 = valid ? acc[mi][nj][hh * 2 + 1] + b1f : 0.f;
                *(float2*)(out + (((size_t)(b * T + t) * U1 + u) << 7) + col) =
                    make_float2(v0, v1);
            }
        }
}

extern "C" void kernel_launch(void* const* d_in, const int* in_sizes, int n_in,
                              void* d_out, int out_size) {
    const float* enc  = (const float*)d_in[0];
    const int*   es   = (const int*)  d_in[1];
    const void*  tgt  =               d_in[2];   // int64 or int32, auto-detected
    const int*   ts   = (const int*)  d_in[3];
    const float* emb  = (const float*)d_in[4];
    const float* W1   = (const float*)d_in[5];
    const float* b1   = (const float*)d_in[6];
    const float* W2   = (const float*)d_in[7];
    const float* b2   = (const float*)d_in[8];
    const float* Wj1  = (const float*)d_in[9];
    const float* bj1  = (const float*)d_in[10];
    const float* Wj2  = (const float*)d_in[11];
    const float* bj2  = (const float*)d_in[12];
    float* out = (float*)d_out;

    static bool attr_done = false;
    if (!attr_done) {
        cudaFuncSetAttribute(k_all,   cudaFuncAttributeMaxDynamicSharedMemorySize, SMEM_ALL);
        cudaFuncSetAttribute(k_joint, cudaFuncAttributeMaxDynamicSharedMemorySize, SMEM_JOINT);
        attr_done = true;
    }

    k_all  <<<257, 256, SMEM_ALL>>>(enc, es, tgt, emb, W1, b1, W2, b2, Wj1, bj1, Wj2);
    k_joint<<<2304, 256, SMEM_JOINT>>>(es, ts, bj2, out);
}